// round 2
// baseline (speedup 1.0000x reference)
#include <cuda_runtime.h>

// Problem constants (fixed shapes from reference: B=16, K=64, H=96, W=96)
constexpr int B = 16;
constexpr int K = 64;
constexpr int H = 96;
constexpr int W = 96;
constexpr int IMG = H * W;                    // 9216 elements per (b,k) image
constexpr int NSTACK = B * K;                 // 1024 images per stack
constexpr long long NBIG = (long long)B * K * H * W;  // 9437184
constexpr int KP_ELEMS = B * 3 * K * 2;       // 6144 floats per keypoint tensor
constexpr int ZETA_ELEMS = B * K;             // 1024

constexpr int THREADS = 256;                  // 8 warps
constexpr int V4_PER_IMG = IMG / 4;           // 2304 float4
constexpr int ITERS = V4_PER_IMG / THREADS;   // 9

__device__ __forceinline__ float sigmoidf(float x) {
    // 1 / (1 + e^-x); __expf rel error ~1e-6, far under the 1e-3 gate
    return 1.0f / (1.0f + __expf(-x));
}

__global__ __launch_bounds__(THREADS)
void fused_decode_kernel(const float* __restrict__ Rk,
                         const float* __restrict__ tfRk,
                         float* __restrict__ Dk_out,
                         float* __restrict__ tfDk_out,
                         float* __restrict__ kp_out,
                         float* __restrict__ tfkp_out,
                         float* __restrict__ zeta_out,
                         float* __restrict__ tfzeta_out)
{
    const int stack = blockIdx.x;             // 0..1023 = b*K + k
    const int which = blockIdx.y;             // 0 = Rk, 1 = tf_Rk

    const float* __restrict__ R  = (which == 0 ? Rk : tfRk) + (size_t)stack * IMG;
    float* __restrict__ D        = (which == 0 ? Dk_out : tfDk_out) + (size_t)stack * IMG;
    float* __restrict__ kp_base  = (which == 0 ? kp_out : tfkp_out);
    float* __restrict__ zeta_base = (which == 0 ? zeta_out : tfzeta_out);

    const int tid = threadIdx.x;

    const float4* __restrict__ R4 = reinterpret_cast<const float4*>(R);
    float4* __restrict__ D4 = reinterpret_cast<float4*>(D);

    // ---- Phase 1: front-batch ALL 9 LDG.128s (MLP_p1 = 9) ----
    float4 r[ITERS];
#pragma unroll
    for (int it = 0; it < ITERS; ++it) {
        r[it] = R4[tid + it * THREADS];
    }

    // ---- Phase 2: sigmoid + store + in-flight moments ----
    float s0 = 0.0f;   // sum d
    float sx = 0.0f;   // sum d * x
    float sy = 0.0f;   // sum d * y

    // 96 floats per row = 24 float4 per row; a float4 never crosses a row.
#pragma unroll
    for (int it = 0; it < ITERS; ++it) {
        const int v = tid + it * THREADS;     // float4 index in [0, 2304)
        float4 d;
        d.x = sigmoidf(r[it].x);
        d.y = sigmoidf(r[it].y);
        d.z = sigmoidf(r[it].z);
        d.w = sigmoidf(r[it].w);
        D4[v] = d;

        const int e = v * 4;                  // element index
        const int h = e / W;
        const int w = e - h * W;              // column of d.x
        const float rowsum = (d.x + d.y) + (d.z + d.w);
        s0 += rowsum;
        sy += rowsum * (float)h;
        sx += d.x * (float)w + d.y * (float)(w + 1)
            + d.z * (float)(w + 2) + d.w * (float)(w + 3);
    }

    // ---- block reduction of (s0, sx, sy) ----
    const int lane = tid & 31;
    const int warp = tid >> 5;
#pragma unroll
    for (int o = 16; o > 0; o >>= 1) {
        s0 += __shfl_down_sync(0xffffffffu, s0, o);
        sx += __shfl_down_sync(0xffffffffu, sx, o);
        sy += __shfl_down_sync(0xffffffffu, sy, o);
    }
    __shared__ float sm0[8], smx[8], smy[8];
    if (lane == 0) { sm0[warp] = s0; smx[warp] = sx; smy[warp] = sy; }
    __syncthreads();

    if (tid == 0) {
        float z = 0.0f, fx = 0.0f, fy = 0.0f;
#pragma unroll
        for (int i = 0; i < 8; ++i) { z += sm0[i]; fx += smx[i]; fy += smy[i]; }

        // kp = round-half-even of moments / zeta (matches jnp.round)
        const float kx = rintf(fx / z);
        const float ky = rintf(fy / z);
        const int wi = (int)kx;
        const int hi = (int)ky;

        // d at rounded location: recompute sigmoid from the input (1 LDG)
        const float dloc = sigmoidf(R[hi * W + wi]);

        const int b = stack / K;
        const int k = stack - b * K;

        // keypoint layout [B, 3K, 2]: rows k (kp), K+k (kp1), 2K+k (kp2)
        float* kp  = kp_base + ((size_t)b * (3 * K) + k) * 2;
        float* kp1 = kp_base + ((size_t)b * (3 * K) + K + k) * 2;
        float* kp2 = kp_base + ((size_t)b * (3 * K) + 2 * K + k) * 2;
        kp[0]  = kx;
        kp[1]  = ky;
        kp1[0] = truncf(kx + kx * dloc);
        kp1[1] = truncf(ky + ky * dloc);
        kp2[0] = truncf(kx - kx * dloc);
        kp2[1] = truncf(ky - ky * dloc);

        zeta_base[stack] = z;
    }
}

extern "C" void kernel_launch(void* const* d_in, const int* in_sizes, int n_in,
                              void* d_out, int out_size)
{
    const float* Rk   = (const float*)d_in[0];
    const float* tfRk = (const float*)d_in[1];
    // d_in[2], d_in[3] are my_height / my_width scalars — shapes are fixed, ignored.

    float* out = (float*)d_out;
    // Output tuple layout, flattened in order:
    // Dk [B,K,H,W], tf_Dk [B,K,H,W], keypoint [B,3K,2], tf_keypoint [B,3K,2],
    // get_zeta [B,K], tf_get_zeta [B,K]
    float* Dk     = out;
    float* tfDk   = out + NBIG;
    float* kp     = out + 2 * NBIG;
    float* tfkp   = kp + KP_ELEMS;
    float* zeta   = tfkp + KP_ELEMS;
    float* tfzeta = zeta + ZETA_ELEMS;

    dim3 grid(NSTACK, 2);
    fused_decode_kernel<<<grid, THREADS>>>(Rk, tfRk, Dk, tfDk, kp, tfkp, zeta, tfzeta);
}

// round 3
// speedup vs baseline: 1.3031x; 1.3031x over previous
#include <cuda_runtime.h>
#include <cstdint>

// Problem constants (fixed shapes: B=16, K=64, H=96, W=96)
constexpr int B = 16;
constexpr int K = 64;
constexpr int H = 96;
constexpr int W = 96;
constexpr int IMG = H * W;                    // 9216 elements per image
constexpr int IMG_BYTES = IMG * 4;            // 36864 bytes
constexpr int NSTACK = B * K;                 // 1024 images per stack
constexpr long long NBIG = (long long)B * K * H * W;
constexpr int KP_ELEMS = B * 3 * K * 2;       // 6144
constexpr int ZETA_ELEMS = B * K;             // 1024

constexpr int THREADS = 256;                  // 8 warps
constexpr int V4_PER_IMG = IMG / 4;           // 2304 float4
constexpr int ITERS = V4_PER_IMG / THREADS;   // 9

__device__ __forceinline__ float sigmoidf(float x) {
    return 1.0f / (1.0f + __expf(-x));
}

__global__ __launch_bounds__(THREADS)
void fused_decode_kernel(const float* __restrict__ Rk,
                         const float* __restrict__ tfRk,
                         float* __restrict__ Dk_out,
                         float* __restrict__ tfDk_out,
                         float* __restrict__ kp_out,
                         float* __restrict__ tfkp_out,
                         float* __restrict__ zeta_out,
                         float* __restrict__ tfzeta_out)
{
    __shared__ alignas(128) float tile[IMG];          // 36864 B TMA landing zone
    __shared__ alignas(8) unsigned long long mbar;
    __shared__ float sm0[8], smx[8], smy[8];

    const int stack = blockIdx.x;             // 0..1023
    const int which = blockIdx.y;             // 0 = Rk, 1 = tf_Rk

    const float* __restrict__ R  = (which == 0 ? Rk : tfRk) + (size_t)stack * IMG;
    float* __restrict__ D        = (which == 0 ? Dk_out : tfDk_out) + (size_t)stack * IMG;
    float* __restrict__ kp_base  = (which == 0 ? kp_out : tfkp_out);
    float* __restrict__ zeta_base = (which == 0 ? zeta_out : tfzeta_out);

    const int tid = threadIdx.x;
    const uint32_t mbar_sa = (uint32_t)__cvta_generic_to_shared(&mbar);
    const uint32_t tile_sa = (uint32_t)__cvta_generic_to_shared(tile);

    // ---- TMA bulk load: whole image (36 KB) in ONE in-flight transaction ----
    if (tid == 0) {
        asm volatile("mbarrier.init.shared.b64 [%0], %1;"
                     :: "r"(mbar_sa), "r"(1) : "memory");
    }
    __syncthreads();
    if (tid == 0) {
        asm volatile("mbarrier.arrive.expect_tx.shared.b64 _, [%0], %1;"
                     :: "r"(mbar_sa), "r"(IMG_BYTES) : "memory");
        asm volatile("cp.async.bulk.shared::cta.global.mbarrier::complete_tx::bytes "
                     "[%0], [%1], %2, [%3];"
                     :: "r"(tile_sa), "l"(R), "r"(IMG_BYTES), "r"(mbar_sa)
                     : "memory");
    }
    // All threads wait for TMA completion (phase 0)
    {
        uint32_t done = 0;
        while (!done) {
            asm volatile(
                "{\n\t.reg .pred p;\n\t"
                "mbarrier.try_wait.parity.acquire.cta.shared::cta.b64 p, [%1], %2;\n\t"
                "selp.b32 %0, 1, 0, p;\n\t}"
                : "=r"(done) : "r"(mbar_sa), "r"(0u) : "memory");
        }
    }

    // ---- Compute from smem: sigmoid + store + in-flight moments ----
    const float4* __restrict__ T4 = reinterpret_cast<const float4*>(tile);
    float4* __restrict__ D4 = reinterpret_cast<float4*>(D);

    float s0 = 0.0f, sx = 0.0f, sy = 0.0f;

#pragma unroll
    for (int it = 0; it < ITERS; ++it) {
        const int v = tid + it * THREADS;     // float4 index in [0, 2304)
        float4 r = T4[v];
        float4 d;
        d.x = sigmoidf(r.x);
        d.y = sigmoidf(r.y);
        d.z = sigmoidf(r.z);
        d.w = sigmoidf(r.w);
        D4[v] = d;

        const int e = v * 4;
        const int h = e / W;
        const int w = e - h * W;
        const float rowsum = (d.x + d.y) + (d.z + d.w);
        s0 += rowsum;
        sy += rowsum * (float)h;
        // sx = w*rowsum + (0*d.x + 1*d.y + 2*d.z + 3*d.w)
        sx += fmaf((float)w, rowsum, fmaf(3.0f, d.w, fmaf(2.0f, d.z, d.y)));
    }

    // ---- block reduction ----
    const int lane = tid & 31;
    const int warp = tid >> 5;
#pragma unroll
    for (int o = 16; o > 0; o >>= 1) {
        s0 += __shfl_down_sync(0xffffffffu, s0, o);
        sx += __shfl_down_sync(0xffffffffu, sx, o);
        sy += __shfl_down_sync(0xffffffffu, sy, o);
    }
    if (lane == 0) { sm0[warp] = s0; smx[warp] = sx; smy[warp] = sy; }
    __syncthreads();

    if (tid == 0) {
        float z = 0.0f, fx = 0.0f, fy = 0.0f;
#pragma unroll
        for (int i = 0; i < 8; ++i) { z += sm0[i]; fx += smx[i]; fy += smy[i]; }

        const float kx = rintf(fx / z);       // jnp.round = round-half-even = rintf
        const float ky = rintf(fy / z);
        const int wi = (int)kx;
        const int hi = (int)ky;

        // d at rounded location: recompute sigmoid from smem copy (free)
        const float dloc = sigmoidf(tile[hi * W + wi]);

        const int b = stack / K;
        const int k = stack - b * K;

        float* kp  = kp_base + ((size_t)b * (3 * K) + k) * 2;
        float* kp1 = kp_base + ((size_t)b * (3 * K) + K + k) * 2;
        float* kp2 = kp_base + ((size_t)b * (3 * K) + 2 * K + k) * 2;
        kp[0]  = kx;
        kp[1]  = ky;
        kp1[0] = truncf(kx + kx * dloc);
        kp1[1] = truncf(ky + ky * dloc);
        kp2[0] = truncf(kx - kx * dloc);
        kp2[1] = truncf(ky - ky * dloc);

        zeta_base[stack] = z;
    }
}

extern "C" void kernel_launch(void* const* d_in, const int* in_sizes, int n_in,
                              void* d_out, int out_size)
{
    const float* Rk   = (const float*)d_in[0];
    const float* tfRk = (const float*)d_in[1];

    float* out = (float*)d_out;
    float* Dk     = out;
    float* tfDk   = out + NBIG;
    float* kp     = out + 2 * NBIG;
    float* tfkp   = kp + KP_ELEMS;
    float* zeta   = tfkp + KP_ELEMS;
    float* tfzeta = zeta + ZETA_ELEMS;

    dim3 grid(NSTACK, 2);
    fused_decode_kernel<<<grid, THREADS>>>(Rk, tfRk, Dk, tfDk, kp, tfkp, zeta, tfzeta);
}